// round 13
// baseline (speedup 1.0000x reference)
#include <cuda_runtime.h>
#include <cstdint>
#include <math.h>

#define BATCH 8192
#define UNITS 2048
#define IN_DIM 2048

// ---------------- tiling constants ----------------
#define BM 128
#define BN 256
#define BK 32
#define AS_STRIDE 36          // BK + 4  -> A frag bank = 4*grp + tig  (bijective)
#define BS_STRIDE 264         // BN + 8  -> B frag bank = 8*tig + grp  (bijective; 264%32==8)
#define AS_FLOATS (BM * AS_STRIDE)              // 4608
#define BS_FLOATS (BK * BS_STRIDE)              // 8448
#define STAGE_FLOATS (AS_FLOATS + BS_FLOATS)    // 13056
#define NSTAGE 3
#define SMEM_BYTES (NSTAGE * STAGE_FLOATS * 4)  // 156672 (triple buffered)
#define KT_PER_PASS (IN_DIM / BK)               // 64

// Scratch planes (64 MB each):
//   0: r_pre, later overwritten by rh = sigmoid(r_pre+br)*h
//   1: u_pre
//   2: xh
//   3: hh = rh @ Wh[:,2U:3U]
__device__ __align__(16) float g_scratch[4ull * BATCH * UNITS];

// ---------------- helpers ----------------
__device__ __forceinline__ uint32_t f2tf32(float x) {
    uint32_t r;
    asm("cvt.rna.tf32.f32 %0, %1;" : "=r"(r) : "f"(x));
    return r;
}

__device__ __forceinline__ void cp_async16(void* smem_ptr, const void* gmem_ptr) {
    uint32_t s = (uint32_t)__cvta_generic_to_shared(smem_ptr);
    asm volatile("cp.async.cg.shared.global [%0], [%1], 16;" :: "r"(s), "l"(gmem_ptr));
}

__device__ __forceinline__ void mma_tf32(float c[4], const uint32_t a[4], const uint32_t b[2]) {
    asm volatile(
        "mma.sync.aligned.m16n8k8.row.col.f32.tf32.tf32.f32 "
        "{%0,%1,%2,%3}, {%4,%5,%6,%7}, {%8,%9}, {%0,%1,%2,%3};"
        : "+f"(c[0]), "+f"(c[1]), "+f"(c[2]), "+f"(c[3])
        : "r"(a[0]), "r"(a[1]), "r"(a[2]), "r"(a[3]), "r"(b[0]), "r"(b[1]));
}

// Stage one (BMxBK A-tile, BKxBN B-tile) via cp.async; one commit group.
__device__ __forceinline__ void load_tile(float* stage, const float* __restrict__ A,
                                          const float* __restrict__ B,
                                          int m0, int n0, int colbase, int kt, int tid) {
    float* As = stage;
    float* Bs = stage + AS_FLOATS;
#pragma unroll
    for (int i = 0; i < 4; i++) {                       // 128x32 A tile: 1024 float4
        int idx = tid + i * 256;
        int row = idx >> 3, c4 = idx & 7;
        const float* src = A + (size_t)(m0 + row) * IN_DIM + kt * BK + c4 * 4;
        cp_async16(As + row * AS_STRIDE + c4 * 4, src);
    }
#pragma unroll
    for (int i = 0; i < 8; i++) {                       // 32x256 B tile: 2048 float4
        int idx = tid + i * 256;
        int row = idx >> 6, c4 = idx & 63;
        const float* src = B + (size_t)(kt * BK + row) * (3 * UNITS) + colbase + n0 + c4 * 4;
        cp_async16(Bs + row * BS_STRIDE + c4 * 4, src);
    }
    asm volatile("cp.async.commit_group;");
}

// ---------------- GEMM kernel ----------------
// phase 0, blockIdx.z selects the plane:
//   0: r_pre = x@Wi[:,0:U]  + h@Wh[:,0:U]   (K = 4096, two passes)
//   1: u_pre = x@Wi[:,U:2U] + h@Wh[:,U:2U]  (K = 4096, two passes)
//   2: xh    = x@Wi[:,2U:3U]                (K = 2048)
// phase 1 (blockIdx.z == 0):
//   3: hh    = rh@Wh[:,2U:3U]  where rh = g_scratch plane 0  (K = 2048)
__global__ void __launch_bounds__(256, 1) gru_gemm_kernel(
    const float* __restrict__ x, const float* __restrict__ h,
    const float* __restrict__ Wi, const float* __restrict__ Wh, int phase) {
    extern __shared__ float smem[];

    const float* Apass[2];
    const float* Bpass[2];
    int npass, colbase;
    float* out;
    if (phase == 0) {
        const int g = blockIdx.z;
        if (g == 0)      { Apass[0] = x; Bpass[0] = Wi; Apass[1] = h; Bpass[1] = Wh; npass = 2; colbase = 0; }
        else if (g == 1) { Apass[0] = x; Bpass[0] = Wi; Apass[1] = h; Bpass[1] = Wh; npass = 2; colbase = UNITS; }
        else             { Apass[0] = x; Bpass[0] = Wi; Apass[1] = x; Bpass[1] = Wi; npass = 1; colbase = 2 * UNITS; }
        out = g_scratch + (size_t)g * BATCH * UNITS;
    } else {
        const float* rh = g_scratch;                 // plane 0 (overwritten with rh)
        Apass[0] = rh; Bpass[0] = Wh; Apass[1] = rh; Bpass[1] = Wh;
        npass = 1; colbase = 2 * UNITS;
        out = g_scratch + 3ull * BATCH * UNITS;      // plane 3
    }

    const int m0 = blockIdx.y * BM;
    const int n0 = blockIdx.x * BN;
    const int tid = threadIdx.x;
    const int lane = tid & 31;
    const int warp = tid >> 5;
    const int warp_m = warp >> 2;  // 2 warps along M (64 rows each)
    const int warp_n = warp & 3;   // 4 warps along N (64 cols each)
    const int grp = lane >> 2;     // 0..7
    const int tig = lane & 3;      // 0..3

    float acc[4][8][4];
#pragma unroll
    for (int mt = 0; mt < 4; mt++)
#pragma unroll
        for (int nt = 0; nt < 8; nt++)
#pragma unroll
            for (int c = 0; c < 4; c++) acc[mt][nt][c] = 0.f;

    const int total_kt = npass * KT_PER_PASS;

    // Prologue: prefetch tiles 0 and 1 into stages 0 and 1.
    load_tile(smem, Apass[0], Bpass[0], m0, n0, colbase, 0, tid);
    load_tile(smem + STAGE_FLOATS, Apass[0], Bpass[0], m0, n0, colbase, 1, tid);

    int cur = 0;   // stage holding tile kt
    for (int kt = 0; kt < total_kt; kt++) {
        // Committed groups so far: tiles 0..kt+1. wait_group 1 leaves only the
        // newest (tile kt+1) possibly in flight -> tile kt is resident.
        if (kt + 1 < total_kt) {
            asm volatile("cp.async.wait_group 1;");
        } else {
            asm volatile("cp.async.wait_group 0;");
        }
        __syncthreads();   // (a) tile kt visible to all; (b) all reads of stage
                           // (kt-1)%3 == (kt+2)%3 from iter kt-1 have completed.

        if (kt + 2 < total_kt) {
            const int t = kt + 2;
            const int p = (t >= KT_PER_PASS) ? 1 : 0;
            int nxt = cur + 2; if (nxt >= NSTAGE) nxt -= NSTAGE;
            load_tile(smem + nxt * STAGE_FLOATS, Apass[p], Bpass[p],
                      m0, n0, colbase, t & (KT_PER_PASS - 1), tid);
        }

        const float* As = smem + cur * STAGE_FLOATS;
        const float* Bs = As + AS_FLOATS;
#pragma unroll
        for (int ks = 0; ks < 4; ks++) {
            const int k8 = ks * 8;
            uint32_t a[4][4];
#pragma unroll
            for (int mt = 0; mt < 4; mt++) {
                const int r0 = warp_m * 64 + mt * 16 + grp;
                a[mt][0] = f2tf32(As[r0 * AS_STRIDE + k8 + tig]);
                a[mt][1] = f2tf32(As[(r0 + 8) * AS_STRIDE + k8 + tig]);
                a[mt][2] = f2tf32(As[r0 * AS_STRIDE + k8 + tig + 4]);
                a[mt][3] = f2tf32(As[(r0 + 8) * AS_STRIDE + k8 + tig + 4]);
            }
            uint32_t b[8][2];
#pragma unroll
            for (int nt = 0; nt < 8; nt++) {
                const int n = warp_n * 64 + nt * 8 + grp;
                b[nt][0] = f2tf32(Bs[(k8 + tig) * BS_STRIDE + n]);
                b[nt][1] = f2tf32(Bs[(k8 + tig + 4) * BS_STRIDE + n]);
            }
#pragma unroll
            for (int mt = 0; mt < 4; mt++)
#pragma unroll
                for (int nt = 0; nt < 8; nt++)
                    mma_tf32(acc[mt][nt], a[mt], b[nt]);
        }

        if (++cur >= NSTAGE) cur = 0;
    }

    // write pre-activations to the plane
#pragma unroll
    for (int mt = 0; mt < 4; mt++) {
#pragma unroll
        for (int nt = 0; nt < 8; nt++) {
            const int row = m0 + warp_m * 64 + mt * 16 + grp;
            const int col = n0 + warp_n * 64 + nt * 8 + 2 * tig;
            *(float2*)&out[(size_t)row * UNITS + col] =
                make_float2(acc[mt][nt][0], acc[mt][nt][1]);
            *(float2*)&out[(size_t)(row + 8) * UNITS + col] =
                make_float2(acc[mt][nt][2], acc[mt][nt][3]);
        }
    }
}

// ---------------- elementwise kernels ----------------
__device__ __forceinline__ float sigmoidf_(float z) { return 1.f / (1.f + expf(-z)); }

// rh = sigmoid(r_pre + br) * h, written in place over plane 0.
__global__ void __launch_bounds__(256) gru_reset_kernel(
    const float* __restrict__ h, const float* __restrict__ bias) {
    const size_t total4 = (size_t)BATCH * UNITS / 4;
    size_t i4 = (size_t)blockIdx.x * blockDim.x + threadIdx.x;
    if (i4 >= total4) return;
    const size_t idx = i4 * 4;
    const int j = (int)(idx % UNITS);

    float4 rv = *(const float4*)&g_scratch[idx];
    float4 hv = *(const float4*)&h[idx];
    float4 br = *(const float4*)&bias[j];

    float4 o;
    o.x = sigmoidf_(rv.x + br.x) * hv.x;
    o.y = sigmoidf_(rv.y + br.y) * hv.y;
    o.z = sigmoidf_(rv.z + br.z) * hv.z;
    o.w = sigmoidf_(rv.w + br.w) * hv.w;
    *(float4*)&g_scratch[idx] = o;
}

// h_t = u*h + (1-u)*tanh(xh + hh + bh),  u = sigmoid(u_pre + bu)
__global__ void __launch_bounds__(256) gru_epilogue_kernel(
    const float* __restrict__ h, const float* __restrict__ bias,
    float* __restrict__ out) {
    const size_t total4 = (size_t)BATCH * UNITS / 4;
    size_t i4 = (size_t)blockIdx.x * blockDim.x + threadIdx.x;
    if (i4 >= total4) return;
    const size_t idx = i4 * 4;
    const int j = (int)(idx % UNITS);
    const size_t MN = (size_t)BATCH * UNITS;

    float4 uv = *(const float4*)&g_scratch[MN + idx];       // u_pre
    float4 xh = *(const float4*)&g_scratch[2 * MN + idx];   // xh
    float4 hh = *(const float4*)&g_scratch[3 * MN + idx];   // hh
    float4 hv = *(const float4*)&h[idx];
    float4 bu = *(const float4*)&bias[UNITS + j];
    float4 bh = *(const float4*)&bias[2 * UNITS + j];

    float4 o;
    {
        float u = sigmoidf_(uv.x + bu.x);
        float c = tanhf(xh.x + hh.x + bh.x);
        o.x = u * hv.x + (1.f - u) * c;
    }
    {
        float u = sigmoidf_(uv.y + bu.y);
        float c = tanhf(xh.y + hh.y + bh.y);
        o.y = u * hv.y + (1.f - u) * c;
    }
    {
        float u = sigmoidf_(uv.z + bu.z);
        float c = tanhf(xh.z + hh.z + bh.z);
        o.z = u * hv.z + (1.f - u) * c;
    }
    {
        float u = sigmoidf_(uv.w + bu.w);
        float c = tanhf(xh.w + hh.w + bh.w);
        o.w = u * hv.w + (1.f - u) * c;
    }
    *(float4*)&out[idx] = o;
}

// ---------------- launch ----------------
extern "C" void kernel_launch(void* const* d_in, const int* in_sizes, int n_in,
                              void* d_out, int out_size) {
    const float* x    = (const float*)d_in[0];  // [8192, 2048]
    const float* h    = (const float*)d_in[1];  // [8192, 2048]
    const float* Wi   = (const float*)d_in[2];  // [2048, 6144]
    const float* Wh   = (const float*)d_in[3];  // [2048, 6144]
    const float* bias = (const float*)d_in[4];  // [6144]
    float* out = (float*)d_out;                 // [8192, 2048]
    (void)in_sizes; (void)n_in; (void)out_size;

    cudaFuncSetAttribute(gru_gemm_kernel,
                         cudaFuncAttributeMaxDynamicSharedMemorySize, SMEM_BYTES);

    const size_t total4 = (size_t)BATCH * UNITS / 4;
    const unsigned eblocks = (unsigned)((total4 + 255) / 256);

    // 1) r_pre, u_pre, xh
    gru_gemm_kernel<<<dim3(UNITS / BN, BATCH / BM, 3), 256, SMEM_BYTES>>>(x, h, Wi, Wh, 0);
    // 2) rh = sigmoid(r_pre + br) * h   (in place, plane 0)
    gru_reset_kernel<<<eblocks, 256>>>(h, bias);
    // 3) hh = rh @ Wh[:, 2U:3U]
    gru_gemm_kernel<<<dim3(UNITS / BN, BATCH / BM, 1), 256, SMEM_BYTES>>>(x, h, Wi, Wh, 1);
    // 4) blend
    gru_epilogue_kernel<<<eblocks, 256>>>(h, bias, out);
}

// round 14
// speedup vs baseline: 1.0601x; 1.0601x over previous
#include <cuda_runtime.h>
#include <cstdint>
#include <math.h>

#define BATCH 8192
#define UNITS 2048
#define IN_DIM 2048
#define MN ((size_t)BATCH * UNITS)            // 16,777,216
#define WELEMS ((size_t)IN_DIM * 3 * UNITS)   // 12,582,912

// ---------------- tiling constants ----------------
#define BM 128
#define BN 256
#define BK 32
#define AS_STRIDE 36          // BK + 4  -> A frag bank = 4*grp + tig  (bijective)
#define BS_STRIDE 264         // BN + 8  -> B frag bank = 8*tig + grp  (bijective; 264%32==8)
#define AS_FLOATS (BM * AS_STRIDE)              // 4608
#define BS_FLOATS (BK * BS_STRIDE)              // 8448
#define STAGE_FLOATS (AS_FLOATS + BS_FLOATS)    // 13056
#define NSTAGE 3
#define SMEM_BYTES (NSTAGE * STAGE_FLOATS * 4)  // 156672 (triple buffered)
#define KT_PER_PASS (IN_DIM / BK)               // 64

// Scratch layout (floats):
//   [0, MN)        r_pre, later overwritten by rh~ = tf32(sigmoid(r_pre+br)*h)
//   [MN, 2MN)      u_pre
//   [2MN, 3MN)     xh
//   [3MN, 4MN)     x~  (tf32-rounded x)
//   [4MN, 5MN)     h~  (tf32-rounded h)
//   [5MN, 5MN+W)   Wi~ (tf32-rounded)
//   [5MN+W, +2W)   Wh~ (tf32-rounded)
#define P_R  0
#define P_U  (MN)
#define P_XH (2 * MN)
#define P_X  (3 * MN)
#define P_H  (4 * MN)
#define P_WI (5 * MN)
#define P_WH (5 * MN + WELEMS)
__device__ __align__(16) float g_scratch[5 * MN + 2 * WELEMS];

// ---------------- helpers ----------------
__device__ __forceinline__ uint32_t f2tf32(float x) {
    uint32_t r;
    asm("cvt.rna.tf32.f32 %0, %1;" : "=r"(r) : "f"(x));
    return r;
}

__device__ __forceinline__ void cp_async16(void* smem_ptr, const void* gmem_ptr) {
    uint32_t s = (uint32_t)__cvta_generic_to_shared(smem_ptr);
    asm volatile("cp.async.cg.shared.global [%0], [%1], 16;" :: "r"(s), "l"(gmem_ptr));
}

__device__ __forceinline__ void mma_tf32(float c[4], const uint32_t a[4], const uint32_t b[2]) {
    asm volatile(
        "mma.sync.aligned.m16n8k8.row.col.f32.tf32.tf32.f32 "
        "{%0,%1,%2,%3}, {%4,%5,%6,%7}, {%8,%9}, {%0,%1,%2,%3};"
        : "+f"(c[0]), "+f"(c[1]), "+f"(c[2]), "+f"(c[3])
        : "r"(a[0]), "r"(a[1]), "r"(a[2]), "r"(a[3]), "r"(b[0]), "r"(b[1]));
}

__device__ __forceinline__ float sigmoidf_(float z) { return 1.f / (1.f + expf(-z)); }

// ---------------- tf32 pre-round kernel ----------------
__global__ void __launch_bounds__(256) round_tf32_kernel(
    const float4* __restrict__ src, float4* __restrict__ dst, int n4) {
    int i = blockIdx.x * blockDim.x + threadIdx.x;
    if (i >= n4) return;
    float4 v = src[i];
    float4 o;
    o.x = __uint_as_float(f2tf32(v.x));
    o.y = __uint_as_float(f2tf32(v.y));
    o.z = __uint_as_float(f2tf32(v.z));
    o.w = __uint_as_float(f2tf32(v.w));
    dst[i] = o;
}

// Stage one (BMxBK A-tile, BKxBN B-tile) via cp.async; one commit group.
__device__ __forceinline__ void load_tile(float* stage, const float* __restrict__ A,
                                          const float* __restrict__ B,
                                          int m0, int n0, int colbase, int kt, int tid) {
    float* As = stage;
    float* Bs = stage + AS_FLOATS;
#pragma unroll
    for (int i = 0; i < 4; i++) {                       // 128x32 A tile: 1024 float4
        int idx = tid + i * 256;
        int row = idx >> 3, c4 = idx & 7;
        const float* src = A + (size_t)(m0 + row) * IN_DIM + kt * BK + c4 * 4;
        cp_async16(As + row * AS_STRIDE + c4 * 4, src);
    }
#pragma unroll
    for (int i = 0; i < 8; i++) {                       // 32x256 B tile: 2048 float4
        int idx = tid + i * 256;
        int row = idx >> 6, c4 = idx & 63;
        const float* src = B + (size_t)(kt * BK + row) * (3 * UNITS) + colbase + n0 + c4 * 4;
        cp_async16(Bs + row * BS_STRIDE + c4 * 4, src);
    }
    asm volatile("cp.async.commit_group;");
}

// ---------------- GEMM kernel ----------------
// All A/B operands are pre-rounded tf32 values in g_scratch -> no CVT in the
// inner loop; fragment loads read raw bits.
// phase 0, blockIdx.z selects the plane:
//   0: r_pre = x~@Wi~[:,0:U]  + h~@Wh~[:,0:U]   (K = 4096, two passes)
//   1: u_pre = x~@Wi~[:,U:2U] + h~@Wh~[:,U:2U]  (K = 4096, two passes)
//   2: xh    = x~@Wi~[:,2U:3U]                  (K = 2048)
// phase 1 (blockIdx.z == 0):
//   hh = rh~@Wh~[:,2U:3U]  (K = 2048), blended in-register into h_t -> final_out
__global__ void __launch_bounds__(256, 1) gru_gemm_kernel(
    const float* __restrict__ h_orig, const float* __restrict__ bias,
    float* __restrict__ final_out, int phase) {
    extern __shared__ float smem[];

    const float* Apass[2];
    const float* Bpass[2];
    int npass, colbase;
    float* out = nullptr;
    if (phase == 0) {
        const int g = blockIdx.z;
        const float* xr = g_scratch + P_X;
        const float* hr = g_scratch + P_H;
        const float* Wi = g_scratch + P_WI;
        const float* Wh = g_scratch + P_WH;
        if (g == 0)      { Apass[0] = xr; Bpass[0] = Wi; Apass[1] = hr; Bpass[1] = Wh; npass = 2; colbase = 0; }
        else if (g == 1) { Apass[0] = xr; Bpass[0] = Wi; Apass[1] = hr; Bpass[1] = Wh; npass = 2; colbase = UNITS; }
        else             { Apass[0] = xr; Bpass[0] = Wi; Apass[1] = xr; Bpass[1] = Wi; npass = 1; colbase = 2 * UNITS; }
        out = g_scratch + (size_t)g * MN;
    } else {
        const float* rh = g_scratch + P_R;           // rh~ (pre-rounded by reset kernel)
        const float* Wh = g_scratch + P_WH;
        Apass[0] = rh; Bpass[0] = Wh; Apass[1] = rh; Bpass[1] = Wh;
        npass = 1; colbase = 2 * UNITS;
    }

    const int m0 = blockIdx.y * BM;
    const int n0 = blockIdx.x * BN;
    const int tid = threadIdx.x;
    const int lane = tid & 31;
    const int warp = tid >> 5;
    const int warp_m = warp >> 2;  // 2 warps along M (64 rows each)
    const int warp_n = warp & 3;   // 4 warps along N (64 cols each)
    const int grp = lane >> 2;     // 0..7
    const int tig = lane & 3;      // 0..3

    float acc[4][8][4];
#pragma unroll
    for (int mt = 0; mt < 4; mt++)
#pragma unroll
        for (int nt = 0; nt < 8; nt++)
#pragma unroll
            for (int c = 0; c < 4; c++) acc[mt][nt][c] = 0.f;

    const int total_kt = npass * KT_PER_PASS;

    // Prologue: prefetch tiles 0 and 1 into stages 0 and 1.
    load_tile(smem, Apass[0], Bpass[0], m0, n0, colbase, 0, tid);
    load_tile(smem + STAGE_FLOATS, Apass[0], Bpass[0], m0, n0, colbase, 1, tid);

    int cur = 0;   // stage holding tile kt
    for (int kt = 0; kt < total_kt; kt++) {
        // Committed groups so far: tiles 0..kt+1. wait_group 1 leaves only the
        // newest (tile kt+1) possibly in flight -> tile kt is resident.
        if (kt + 1 < total_kt) {
            asm volatile("cp.async.wait_group 1;");
        } else {
            asm volatile("cp.async.wait_group 0;");
        }
        __syncthreads();   // (a) tile kt visible to all; (b) all reads of stage
                           // (kt-1)%3 == (kt+2)%3 from iter kt-1 have completed.

        if (kt + 2 < total_kt) {
            const int t = kt + 2;
            const int p = (t >= KT_PER_PASS) ? 1 : 0;
            int nxt = cur + 2; if (nxt >= NSTAGE) nxt -= NSTAGE;
            load_tile(smem + nxt * STAGE_FLOATS, Apass[p], Bpass[p],
                      m0, n0, colbase, t & (KT_PER_PASS - 1), tid);
        }

        const uint32_t* As = (const uint32_t*)(smem + cur * STAGE_FLOATS);
        const uint32_t* Bs = As + AS_FLOATS;
#pragma unroll
        for (int ks = 0; ks < 4; ks++) {
            const int k8 = ks * 8;
            uint32_t a[4][4];
#pragma unroll
            for (int mt = 0; mt < 4; mt++) {
                const int r0 = warp_m * 64 + mt * 16 + grp;
                a[mt][0] = As[r0 * AS_STRIDE + k8 + tig];
                a[mt][1] = As[(r0 + 8) * AS_STRIDE + k8 + tig];
                a[mt][2] = As[r0 * AS_STRIDE + k8 + tig + 4];
                a[mt][3] = As[(r0 + 8) * AS_STRIDE + k8 + tig + 4];
            }
            uint32_t b[8][2];
#pragma unroll
            for (int nt = 0; nt < 8; nt++) {
                const int n = warp_n * 64 + nt * 8 + grp;
                b[nt][0] = Bs[(k8 + tig) * BS_STRIDE + n];
                b[nt][1] = Bs[(k8 + tig + 4) * BS_STRIDE + n];
            }
#pragma unroll
            for (int mt = 0; mt < 4; mt++)
#pragma unroll
                for (int nt = 0; nt < 8; nt++)
                    mma_tf32(acc[mt][nt], a[mt], b[nt]);
        }

        if (++cur >= NSTAGE) cur = 0;
    }

    if (phase == 0) {
        // write pre-activations to the plane
#pragma unroll
        for (int mt = 0; mt < 4; mt++) {
#pragma unroll
            for (int nt = 0; nt < 8; nt++) {
                const int row = m0 + warp_m * 64 + mt * 16 + grp;
                const int col = n0 + warp_n * 64 + nt * 8 + 2 * tig;
                *(float2*)&out[(size_t)row * UNITS + col] =
                    make_float2(acc[mt][nt][0], acc[mt][nt][1]);
                *(float2*)&out[(size_t)(row + 8) * UNITS + col] =
                    make_float2(acc[mt][nt][2], acc[mt][nt][3]);
            }
        }
    } else {
        // fused GRU blend: h_t = u*h + (1-u)*tanh(xh + hh + bh)
        const float* up = g_scratch + P_U;
        const float* xp = g_scratch + P_XH;
#pragma unroll
        for (int mt = 0; mt < 4; mt++) {
#pragma unroll
            for (int nt = 0; nt < 8; nt++) {
                const int row = m0 + warp_m * 64 + mt * 16 + grp;
                const int col = n0 + warp_n * 64 + nt * 8 + 2 * tig;
                float2 bu = *(const float2*)&bias[UNITS + col];
                float2 bh = *(const float2*)&bias[2 * UNITS + col];
#pragma unroll
                for (int half = 0; half < 2; half++) {
                    const size_t off = (size_t)(row + half * 8) * UNITS + col;
                    float2 uv = *(const float2*)&up[off];
                    float2 xv = *(const float2*)&xp[off];
                    float2 hv = *(const float2*)&h_orig[off];
                    float hh0 = acc[mt][nt][half * 2 + 0];
                    float hh1 = acc[mt][nt][half * 2 + 1];
                    float u0 = sigmoidf_(uv.x + bu.x);
                    float u1 = sigmoidf_(uv.y + bu.y);
                    float c0 = tanhf(xv.x + hh0 + bh.x);
                    float c1 = tanhf(xv.y + hh1 + bh.y);
                    float2 o;
                    o.x = u0 * hv.x + (1.f - u0) * c0;
                    o.y = u1 * hv.y + (1.f - u1) * c1;
                    *(float2*)&final_out[off] = o;
                }
            }
        }
    }
}

// ---------------- reset kernel ----------------
// rh~ = tf32(sigmoid(r_pre + br) * h), written in place over plane 0.
__global__ void __launch_bounds__(256) gru_reset_kernel(
    const float* __restrict__ h, const float* __restrict__ bias) {
    const size_t total4 = MN / 4;
    size_t i4 = (size_t)blockIdx.x * blockDim.x + threadIdx.x;
    if (i4 >= total4) return;
    const size_t idx = i4 * 4;
    const int j = (int)(idx % UNITS);

    float4 rv = *(const float4*)&g_scratch[P_R + idx];
    float4 hv = *(const float4*)&h[idx];
    float4 br = *(const float4*)&bias[j];

    float4 o;
    o.x = __uint_as_float(f2tf32(sigmoidf_(rv.x + br.x) * hv.x));
    o.y = __uint_as_float(f2tf32(sigmoidf_(rv.y + br.y) * hv.y));
    o.z = __uint_as_float(f2tf32(sigmoidf_(rv.z + br.z) * hv.z));
    o.w = __uint_as_float(f2tf32(sigmoidf_(rv.w + br.w) * hv.w));
    *(float4*)&g_scratch[P_R + idx] = o;
}

// ---------------- launch ----------------
extern "C" void kernel_launch(void* const* d_in, const int* in_sizes, int n_in,
                              void* d_out, int out_size) {
    const float* x    = (const float*)d_in[0];  // [8192, 2048]
    const float* h    = (const float*)d_in[1];  // [8192, 2048]
    const float* Wi   = (const float*)d_in[2];  // [2048, 6144]
    const float* Wh   = (const float*)d_in[3];  // [2048, 6144]
    const float* bias = (const float*)d_in[4];  // [6144]
    float* out = (float*)d_out;                 // [8192, 2048]
    (void)in_sizes; (void)n_in; (void)out_size;

    cudaFuncSetAttribute(gru_gemm_kernel,
                         cudaFuncAttributeMaxDynamicSharedMemorySize, SMEM_BYTES);

    float* scr;
    cudaGetSymbolAddress((void**)&scr, g_scratch);

    // 0) pre-round all GEMM operands to the tf32 grid (bit-identical to
    //    per-use cvt.rna; rounding is idempotent)
    {
        const int xn4 = (int)(MN / 4);        // 4,194,304
        const int wn4 = (int)(WELEMS / 4);    // 3,145,728
        round_tf32_kernel<<<(xn4 + 255) / 256, 256>>>((const float4*)x,  (float4*)(scr + P_X),  xn4);
        round_tf32_kernel<<<(xn4 + 255) / 256, 256>>>((const float4*)h,  (float4*)(scr + P_H),  xn4);
        round_tf32_kernel<<<(wn4 + 255) / 256, 256>>>((const float4*)Wi, (float4*)(scr + P_WI), wn4);
        round_tf32_kernel<<<(wn4 + 255) / 256, 256>>>((const float4*)Wh, (float4*)(scr + P_WH), wn4);
    }

    const size_t total4 = MN / 4;
    const unsigned eblocks = (unsigned)((total4 + 255) / 256);

    // 1) r_pre, u_pre, xh
    gru_gemm_kernel<<<dim3(UNITS / BN, BATCH / BM, 3), 256, SMEM_BYTES>>>(h, bias, out, 0);
    // 2) rh~ = tf32(sigmoid(r_pre + br) * h)   (in place, plane 0)
    gru_reset_kernel<<<eblocks, 256>>>(h, bias);
    // 3) hh = rh~ @ Wh~[:, 2U:3U], fused blend -> out
    gru_gemm_kernel<<<dim3(UNITS / BN, BATCH / BM, 1), 256, SMEM_BYTES>>>(h, bias, out, 1);
}

// round 16
// speedup vs baseline: 1.1001x; 1.0378x over previous
#include <cuda_runtime.h>
#include <cstdint>
#include <math.h>

#define BATCH 8192
#define UNITS 2048
#define IN_DIM 2048
#define MN ((size_t)BATCH * UNITS)            // 16,777,216
#define WELEMS ((size_t)IN_DIM * 3 * UNITS)   // 12,582,912

// ---------------- tiling constants ----------------
#define BM 128
#define BN 128
#define BK 32
#define AS_STRIDE 36          // BK + 4  -> A frag bank = 4*grp + tig  (bijective)
#define BS_STRIDE 136         // BN + 8  -> B frag bank = 8*tig + grp  (bijective; 136%32==8)
#define AS_FLOATS (BM * AS_STRIDE)              // 4608
#define BS_FLOATS (BK * BS_STRIDE)              // 4352
#define STAGE_FLOATS (AS_FLOATS + BS_FLOATS)    // 8960
#define NSTAGE 3
#define SMEM_BYTES (NSTAGE * STAGE_FLOATS * 4)  // 107520; x2 CTAs = 215KB/SM
#define KT_PER_PASS (IN_DIM / BK)               // 64

// Scratch layout (floats):
//   [0, MN)        r_pre, later overwritten by rh~ = tf32(sigmoid(r_pre+br)*h)
//   [MN, 2MN)      u_pre
//   [2MN, 3MN)     xh
//   [3MN, 4MN)     x~  (tf32-rounded x)
//   [4MN, 5MN)     h~  (tf32-rounded h)
//   [5MN, 5MN+W)   Wi~ (tf32-rounded)
//   [5MN+W, +2W)   Wh~ (tf32-rounded)
#define P_R  0
#define P_U  (MN)
#define P_XH (2 * MN)
#define P_X  (3 * MN)
#define P_H  (4 * MN)
#define P_WI (5 * MN)
#define P_WH (5 * MN + WELEMS)
__device__ __align__(16) float g_scratch[5 * MN + 2 * WELEMS];

// ---------------- helpers ----------------
__device__ __forceinline__ uint32_t f2tf32(float x) {
    uint32_t r;
    asm("cvt.rna.tf32.f32 %0, %1;" : "=r"(r) : "f"(x));
    return r;
}

__device__ __forceinline__ void cp_async16(void* smem_ptr, const void* gmem_ptr) {
    uint32_t s = (uint32_t)__cvta_generic_to_shared(smem_ptr);
    asm volatile("cp.async.cg.shared.global [%0], [%1], 16;" :: "r"(s), "l"(gmem_ptr));
}

__device__ __forceinline__ void mma_tf32(float c[4], const uint32_t a[4], const uint32_t b[2]) {
    asm volatile(
        "mma.sync.aligned.m16n8k8.row.col.f32.tf32.tf32.f32 "
        "{%0,%1,%2,%3}, {%4,%5,%6,%7}, {%8,%9}, {%0,%1,%2,%3};"
        : "+f"(c[0]), "+f"(c[1]), "+f"(c[2]), "+f"(c[3])
        : "r"(a[0]), "r"(a[1]), "r"(a[2]), "r"(a[3]), "r"(b[0]), "r"(b[1]));
}

__device__ __forceinline__ float sigmoidf_(float z) { return 1.f / (1.f + expf(-z)); }

// ---------------- tf32 pre-round kernel ----------------
__global__ void __launch_bounds__(256) round_tf32_kernel(
    const float4* __restrict__ src, float4* __restrict__ dst, int n4) {
    int i = blockIdx.x * blockDim.x + threadIdx.x;
    if (i >= n4) return;
    float4 v = src[i];
    float4 o;
    o.x = __uint_as_float(f2tf32(v.x));
    o.y = __uint_as_float(f2tf32(v.y));
    o.z = __uint_as_float(f2tf32(v.z));
    o.w = __uint_as_float(f2tf32(v.w));
    dst[i] = o;
}

// Stage one (BMxBK A-tile, BKxBN B-tile) via cp.async; one commit group.
__device__ __forceinline__ void load_tile(float* stage, const float* __restrict__ A,
                                          const float* __restrict__ B,
                                          int m0, int n0, int colbase, int kt, int tid) {
    float* As = stage;
    float* Bs = stage + AS_FLOATS;
#pragma unroll
    for (int i = 0; i < 4; i++) {                       // 128x32 A tile: 1024 float4
        int idx = tid + i * 256;
        int row = idx >> 3, c4 = idx & 7;
        const float* src = A + (size_t)(m0 + row) * IN_DIM + kt * BK + c4 * 4;
        cp_async16(As + row * AS_STRIDE + c4 * 4, src);
    }
#pragma unroll
    for (int i = 0; i < 4; i++) {                       // 32x128 B tile: 1024 float4
        int idx = tid + i * 256;
        int row = idx >> 5, c4 = idx & 31;
        const float* src = B + (size_t)(kt * BK + row) * (3 * UNITS) + colbase + n0 + c4 * 4;
        cp_async16(Bs + row * BS_STRIDE + c4 * 4, src);
    }
    asm volatile("cp.async.commit_group;");
}

// ---------------- GEMM kernel ----------------
// 128x128 block tile, 8 warps as 2(M)x4(N), 64x32 warp tiles, 2 CTAs/SM.
// All A/B operands are pre-rounded tf32 values in g_scratch -> no CVT inner loop.
// phase 0, blockIdx.z selects the plane:
//   0: r_pre = x~@Wi~[:,0:U]  + h~@Wh~[:,0:U]   (K = 4096, two passes)
//   1: u_pre = x~@Wi~[:,U:2U] + h~@Wh~[:,U:2U]  (K = 4096, two passes)
//   2: xh    = x~@Wi~[:,2U:3U]                  (K = 2048)
// phase 1 (blockIdx.z == 0):
//   hh = rh~@Wh~[:,2U:3U]  (K = 2048), blended in-register into h_t -> final_out
__global__ void __launch_bounds__(256, 2) gru_gemm_kernel(
    const float* __restrict__ h_orig, const float* __restrict__ bias,
    float* __restrict__ final_out, int phase) {
    extern __shared__ float smem[];

    const float* Apass[2];
    const float* Bpass[2];
    int npass, colbase;
    float* out = nullptr;
    if (phase == 0) {
        const int g = blockIdx.z;
        const float* xr = g_scratch + P_X;
        const float* hr = g_scratch + P_H;
        const float* Wi = g_scratch + P_WI;
        const float* Wh = g_scratch + P_WH;
        if (g == 0)      { Apass[0] = xr; Bpass[0] = Wi; Apass[1] = hr; Bpass[1] = Wh; npass = 2; colbase = 0; }
        else if (g == 1) { Apass[0] = xr; Bpass[0] = Wi; Apass[1] = hr; Bpass[1] = Wh; npass = 2; colbase = UNITS; }
        else             { Apass[0] = xr; Bpass[0] = Wi; Apass[1] = xr; Bpass[1] = Wi; npass = 1; colbase = 2 * UNITS; }
        out = g_scratch + (size_t)g * MN;
    } else {
        const float* rh = g_scratch + P_R;           // rh~ (pre-rounded by reset kernel)
        const float* Wh = g_scratch + P_WH;
        Apass[0] = rh; Bpass[0] = Wh; Apass[1] = rh; Bpass[1] = Wh;
        npass = 1; colbase = 2 * UNITS;
    }

    const int m0 = blockIdx.y * BM;
    const int n0 = blockIdx.x * BN;
    const int tid = threadIdx.x;
    const int lane = tid & 31;
    const int warp = tid >> 5;
    const int warp_m = warp >> 2;  // 2 warps along M (64 rows each)
    const int warp_n = warp & 3;   // 4 warps along N (32 cols each)
    const int grp = lane >> 2;     // 0..7
    const int tig = lane & 3;      // 0..3

    float acc[4][4][4];
#pragma unroll
    for (int mt = 0; mt < 4; mt++)
#pragma unroll
        for (int nt = 0; nt < 4; nt++)
#pragma unroll
            for (int c = 0; c < 4; c++) acc[mt][nt][c] = 0.f;

    const int total_kt = npass * KT_PER_PASS;

    // Prologue: prefetch tiles 0 and 1 into stages 0 and 1.
    load_tile(smem, Apass[0], Bpass[0], m0, n0, colbase, 0, tid);
    load_tile(smem + STAGE_FLOATS, Apass[0], Bpass[0], m0, n0, colbase, 1, tid);

    int cur = 0;   // stage holding tile kt
    for (int kt = 0; kt < total_kt; kt++) {
        // Committed groups so far: tiles 0..kt+1. wait_group 1 leaves only the
        // newest (tile kt+1) possibly in flight -> tile kt is resident.
        if (kt + 1 < total_kt) {
            asm volatile("cp.async.wait_group 1;");
        } else {
            asm volatile("cp.async.wait_group 0;");
        }
        __syncthreads();   // (a) tile kt visible to all; (b) all reads of stage
                           // (kt-1)%3 == (kt+2)%3 from iter kt-1 have completed.

        if (kt + 2 < total_kt) {
            const int t = kt + 2;
            const int p = (t >= KT_PER_PASS) ? 1 : 0;
            int nxt = cur + 2; if (nxt >= NSTAGE) nxt -= NSTAGE;
            load_tile(smem + nxt * STAGE_FLOATS, Apass[p], Bpass[p],
                      m0, n0, colbase, t & (KT_PER_PASS - 1), tid);
        }

        const uint32_t* As = (const uint32_t*)(smem + cur * STAGE_FLOATS);
        const uint32_t* Bs = As + AS_FLOATS;
#pragma unroll
        for (int ks = 0; ks < 4; ks++) {
            const int k8 = ks * 8;
            uint32_t a[4][4];
#pragma unroll
            for (int mt = 0; mt < 4; mt++) {
                const int r0 = warp_m * 64 + mt * 16 + grp;
                a[mt][0] = As[r0 * AS_STRIDE + k8 + tig];
                a[mt][1] = As[(r0 + 8) * AS_STRIDE + k8 + tig];
                a[mt][2] = As[r0 * AS_STRIDE + k8 + tig + 4];
                a[mt][3] = As[(r0 + 8) * AS_STRIDE + k8 + tig + 4];
            }
            uint32_t b[4][2];
#pragma unroll
            for (int nt = 0; nt < 4; nt++) {
                const int n = warp_n * 32 + nt * 8 + grp;
                b[nt][0] = Bs[(k8 + tig) * BS_STRIDE + n];
                b[nt][1] = Bs[(k8 + tig + 4) * BS_STRIDE + n];
            }
#pragma unroll
            for (int mt = 0; mt < 4; mt++)
#pragma unroll
                for (int nt = 0; nt < 4; nt++)
                    mma_tf32(acc[mt][nt], a[mt], b[nt]);
        }

        if (++cur >= NSTAGE) cur = 0;
    }

    if (phase == 0) {
        // write pre-activations to the plane
#pragma unroll
        for (int mt = 0; mt < 4; mt++) {
#pragma unroll
            for (int nt = 0; nt < 4; nt++) {
                const int row = m0 + warp_m * 64 + mt * 16 + grp;
                const int col = n0 + warp_n * 32 + nt * 8 + 2 * tig;
                *(float2*)&out[(size_t)row * UNITS + col] =
                    make_float2(acc[mt][nt][0], acc[mt][nt][1]);
                *(float2*)&out[(size_t)(row + 8) * UNITS + col] =
                    make_float2(acc[mt][nt][2], acc[mt][nt][3]);
            }
        }
    } else {
        // fused GRU blend: h_t = u*h + (1-u)*tanh(xh + hh + bh)
        const float* up = g_scratch + P_U;
        const float* xp = g_scratch + P_XH;
#pragma unroll
        for (int mt = 0; mt < 4; mt++) {
#pragma unroll
            for (int nt = 0; nt < 4; nt++) {
                const int row = m0 + warp_m * 64 + mt * 16 + grp;
                const int col = n0 + warp_n * 32 + nt * 8 + 2 * tig;
                float2 bu = *(const float2*)&bias[UNITS + col];
                float2 bh = *(const float2*)&bias[2 * UNITS + col];
#pragma unroll
                for (int half = 0; half < 2; half++) {
                    const size_t off = (size_t)(row + half * 8) * UNITS + col;
                    float2 uv = *(const float2*)&up[off];
                    float2 xv = *(const float2*)&xp[off];
                    float2 hv = *(const float2*)&h_orig[off];
                    float hh0 = acc[mt][nt][half * 2 + 0];
                    float hh1 = acc[mt][nt][half * 2 + 1];
                    float u0 = sigmoidf_(uv.x + bu.x);
                    float u1 = sigmoidf_(uv.y + bu.y);
                    float c0 = tanhf(xv.x + hh0 + bh.x);
                    float c1 = tanhf(xv.y + hh1 + bh.y);
                    float2 o;
                    o.x = u0 * hv.x + (1.f - u0) * c0;
                    o.y = u1 * hv.y + (1.f - u1) * c1;
                    *(float2*)&final_out[off] = o;
                }
            }
        }
    }
}

// ---------------- reset kernel ----------------
// rh~ = tf32(sigmoid(r_pre + br) * h), written in place over plane 0.
__global__ void __launch_bounds__(256) gru_reset_kernel(
    const float* __restrict__ h, const float* __restrict__ bias) {
    const size_t total4 = MN / 4;
    size_t i4 = (size_t)blockIdx.x * blockDim.x + threadIdx.x;
    if (i4 >= total4) return;
    const size_t idx = i4 * 4;
    const int j = (int)(idx % UNITS);

    float4 rv = *(const float4*)&g_scratch[P_R + idx];
    float4 hv = *(const float4*)&h[idx];
    float4 br = *(const float4*)&bias[j];

    float4 o;
    o.x = __uint_as_float(f2tf32(sigmoidf_(rv.x + br.x) * hv.x));
    o.y = __uint_as_float(f2tf32(sigmoidf_(rv.y + br.y) * hv.y));
    o.z = __uint_as_float(f2tf32(sigmoidf_(rv.z + br.z) * hv.z));
    o.w = __uint_as_float(f2tf32(sigmoidf_(rv.w + br.w) * hv.w));
    *(float4*)&g_scratch[P_R + idx] = o;
}

// ---------------- launch ----------------
extern "C" void kernel_launch(void* const* d_in, const int* in_sizes, int n_in,
                              void* d_out, int out_size) {
    const float* x    = (const float*)d_in[0];  // [8192, 2048]
    const float* h    = (const float*)d_in[1];  // [8192, 2048]
    const float* Wi   = (const float*)d_in[2];  // [2048, 6144]
    const float* Wh   = (const float*)d_in[3];  // [2048, 6144]
    const float* bias = (const float*)d_in[4];  // [6144]
    float* out = (float*)d_out;                 // [8192, 2048]
    (void)in_sizes; (void)n_in; (void)out_size;

    cudaFuncSetAttribute(gru_gemm_kernel,
                         cudaFuncAttributeMaxDynamicSharedMemorySize, SMEM_BYTES);

    float* scr;
    cudaGetSymbolAddress((void**)&scr, g_scratch);

    // 0) pre-round all GEMM operands to the tf32 grid (bit-identical to
    //    per-use cvt.rna; rounding is idempotent)
    {
        const int xn4 = (int)(MN / 4);        // 4,194,304
        const int wn4 = (int)(WELEMS / 4);    // 3,145,728
        round_tf32_kernel<<<(xn4 + 255) / 256, 256>>>((const float4*)x,  (float4*)(scr + P_X),  xn4);
        round_tf32_kernel<<<(xn4 + 255) / 256, 256>>>((const float4*)h,  (float4*)(scr + P_H),  xn4);
        round_tf32_kernel<<<(wn4 + 255) / 256, 256>>>((const float4*)Wi, (float4*)(scr + P_WI), wn4);
        round_tf32_kernel<<<(wn4 + 255) / 256, 256>>>((const float4*)Wh, (float4*)(scr + P_WH), wn4);
    }

    const size_t total4 = MN / 4;
    const unsigned eblocks = (unsigned)((total4 + 255) / 256);

    // 1) r_pre, u_pre, xh
    gru_gemm_kernel<<<dim3(UNITS / BN, BATCH / BM, 3), 256, SMEM_BYTES>>>(h, bias, out, 0);
    // 2) rh~ = tf32(sigmoid(r_pre + br) * h)   (in place, plane 0)
    gru_reset_kernel<<<eblocks, 256>>>(h, bias);
    // 3) hh = rh~ @ Wh~[:, 2U:3U], fused blend -> out
    gru_gemm_kernel<<<dim3(UNITS / BN, BATCH / BM, 1), 256, SMEM_BYTES>>>(h, bias, out, 1);
}